// round 9
// baseline (speedup 1.0000x reference)
#include <cuda_runtime.h>
#include <math.h>

#define NU   2560
#define NI   3584
#define NTOT 6144
#define EDIM 64
#define NE   (NTOT*EDIM)
#define DQK  256
#define KTOP 5
#define RS   68          // smem row stride (floats); 16B-aligned rows for cp.async
#define NSPLIT 3
#define TJ   128

// ---- device scratch ----
// one contiguous zero-init region: [ego1 | ego2 | B]  (single memsetAsync)
__device__ float g_zbuf[3*NE];
__device__ float g_cv[NSPLIT*NTOT*KTOP];
__device__ int   g_cj[NSPLIT*NTOT*KTOP];
__device__ float g_q [NTOT*DQK];
__device__ float g_k [NTOT*DQK];
__device__ float g_v [NTOT*DQK];

#define EGO1 (g_zbuf)
#define EGO2 (g_zbuf + NE)
#define BB   (g_zbuf + 2*NE)

typedef unsigned long long ull;

__device__ __forceinline__ ull fma2(ull a, ull b, ull c) {
    ull d;
    asm("fma.rn.f32x2 %0, %1, %2, %3;" : "=l"(d) : "l"(a), "l"(b), "l"(c));
    return d;
}
__device__ __forceinline__ float pairsum(ull p) {
    return __uint_as_float((unsigned)p) + __uint_as_float((unsigned)(p >> 32));
}
__device__ __forceinline__ void cp16(void* dst, const void* src) {
    unsigned s = (unsigned)__cvta_generic_to_shared(dst);
    asm volatile("cp.async.cg.shared.global [%0], [%1], 16;" :: "r"(s), "l"(src) : "memory");
}

// ---------------------------------------------------------------------------
// spmm reading embeddings directly: dst[row] += val * emb[col]
__global__ void spmm_emb(const int* __restrict__ rows, const int* __restrict__ cols,
                         const float* __restrict__ vals,
                         const float* __restrict__ ue, const float* __restrict__ ie,
                         float* __restrict__ dst, int nnz) {
    int t = blockIdx.x * blockDim.x + threadIdx.x;
    int nz = t >> 4;
    if (nz >= nnz) return;
    int e = (t & 15) * 4;
    float v = vals[nz];
    int c = cols[nz];
    const float* src = (c < NU) ? (ue + c*EDIM) : (ie + (c - NU)*EDIM);
    float4 s = *(const float4*)&src[e];
    float* d = &dst[rows[nz]*EDIM + e];
    asm volatile("red.global.add.v4.f32 [%0], {%1,%2,%3,%4};"
                 :: "l"(d), "f"(v*s.x), "f"(v*s.y), "f"(v*s.z), "f"(v*s.w) : "memory");
}

// dst[row] += scale * val * src[col]
__global__ void spmm_atomic(const int* __restrict__ rows, const int* __restrict__ cols,
                            const float* __restrict__ vals,
                            const float* __restrict__ src, float* __restrict__ dst,
                            float scale, int nnz) {
    int t = blockIdx.x * blockDim.x + threadIdx.x;
    int nz = t >> 4;
    if (nz >= nnz) return;
    int e = (t & 15) * 4;
    float v = vals[nz] * scale;
    float4 s = *(const float4*)&src[cols[nz]*EDIM + e];
    float* d = &dst[rows[nz]*EDIM + e];
    asm volatile("red.global.add.v4.f32 [%0], {%1,%2,%3,%4};"
                 :: "l"(d), "f"(v*s.x), "f"(v*s.y), "f"(v*s.z), "f"(v*s.w) : "memory");
}

// ---------------------------------------------------------------------------
// Fused sim GEMM + per-row top-5 over one j-third. 32 rows/block, TJ=128,
// per-thread 4x4, A-tile = ego2 + B staged to smem, double-buffered Es.
__global__ __launch_bounds__(256, 2) void topk_pass() {
    __shared__ float Bs[32*RS];
    extern __shared__ float Es[];       // 2 * TJ * RS floats

    int tid  = threadIdx.x;
    int tx   = tid & 31;
    int w    = tid >> 5;
    int row0 = blockIdx.x * 32;
    int jbase = blockIdx.y * (NTOT / NSPLIT);
    const int NCH = (NTOT / NSPLIT) / TJ;   // 16

    for (int idx = tid; idx < 32*32; idx += 256) {
        int r = idx >> 5, e2 = idx & 31;
        float2 a = *(const float2*)&EGO2[(row0 + r)*EDIM + 2*e2];
        float2 b = *(const float2*)&BB  [(row0 + r)*EDIM + 2*e2];
        a.x += b.x; a.y += b.y;
        *(float2*)&Bs[r*RS + 2*e2] = a;
    }

    for (int idx = tid; idx < TJ*16; idx += 256) {
        int c = idx >> 4, q2 = idx & 15;
        cp16(&Es[c*RS + q2*4], &EGO2[(jbase + c)*EDIM + q2*4]);
    }
    asm volatile("cp.async.commit_group;");

    float tv[4][KTOP];
    int   ti[4][KTOP];
#pragma unroll
    for (int i = 0; i < 4; i++)
#pragma unroll
        for (int s = 0; s < KTOP; s++) { tv[i][s] = -INFINITY; ti[i][s] = 0x7fffffff; }

    for (int k = 0; k < NCH; k++) {
        int cur = (k & 1) * TJ * RS;
        if (k + 1 < NCH) {
            int nxt = ((k + 1) & 1) * TJ * RS;
            int jn = jbase + (k + 1) * TJ;
            for (int idx = tid; idx < TJ*16; idx += 256) {
                int c = idx >> 4, q2 = idx & 15;
                cp16(&Es[nxt + c*RS + q2*4], &EGO2[(jn + c)*EDIM + q2*4]);
            }
            asm volatile("cp.async.commit_group;");
            asm volatile("cp.async.wait_group 1;");
        } else {
            asm volatile("cp.async.wait_group 0;");
        }
        __syncthreads();

        ull acc[4][4];
#pragma unroll
        for (int i = 0; i < 4; i++)
#pragma unroll
            for (int c = 0; c < 4; c++) acc[i][c] = 0ull;

#pragma unroll 4
        for (int u = 0; u < 16; u++) {
            float4 a0 = *(const float4*)&Bs[(w*4 + 0)*RS + u*4];
            float4 a1 = *(const float4*)&Bs[(w*4 + 1)*RS + u*4];
            float4 a2 = *(const float4*)&Bs[(w*4 + 2)*RS + u*4];
            float4 a3 = *(const float4*)&Bs[(w*4 + 3)*RS + u*4];
            float4 b0 = *(const float4*)&Es[cur + (tx +  0)*RS + u*4];
            float4 b1 = *(const float4*)&Es[cur + (tx + 32)*RS + u*4];
            float4 b2 = *(const float4*)&Es[cur + (tx + 64)*RS + u*4];
            float4 b3 = *(const float4*)&Es[cur + (tx + 96)*RS + u*4];
            const ull* A0 = (const ull*)&a0; const ull* A1 = (const ull*)&a1;
            const ull* A2 = (const ull*)&a2; const ull* A3 = (const ull*)&a3;
            const ull* B0 = (const ull*)&b0; const ull* B1 = (const ull*)&b1;
            const ull* B2 = (const ull*)&b2; const ull* B3 = (const ull*)&b3;
#pragma unroll
            for (int h = 0; h < 2; h++) {
                acc[0][0]=fma2(A0[h],B0[h],acc[0][0]); acc[0][1]=fma2(A0[h],B1[h],acc[0][1]);
                acc[0][2]=fma2(A0[h],B2[h],acc[0][2]); acc[0][3]=fma2(A0[h],B3[h],acc[0][3]);
                acc[1][0]=fma2(A1[h],B0[h],acc[1][0]); acc[1][1]=fma2(A1[h],B1[h],acc[1][1]);
                acc[1][2]=fma2(A1[h],B2[h],acc[1][2]); acc[1][3]=fma2(A1[h],B3[h],acc[1][3]);
                acc[2][0]=fma2(A2[h],B0[h],acc[2][0]); acc[2][1]=fma2(A2[h],B1[h],acc[2][1]);
                acc[2][2]=fma2(A2[h],B2[h],acc[2][2]); acc[2][3]=fma2(A2[h],B3[h],acc[2][3]);
                acc[3][0]=fma2(A3[h],B0[h],acc[3][0]); acc[3][1]=fma2(A3[h],B1[h],acc[3][1]);
                acc[3][2]=fma2(A3[h],B2[h],acc[3][2]); acc[3][3]=fma2(A3[h],B3[h],acc[3][3]);
            }
        }

        // top-5 insert; ascending j + strict > keeps smallest index on ties.
#pragma unroll
        for (int i = 0; i < 4; i++) {
            float v0 = pairsum(acc[i][0]);
            float v1 = pairsum(acc[i][1]);
            float v2 = pairsum(acc[i][2]);
            float v3 = pairsum(acc[i][3]);
            float m4 = fmaxf(fmaxf(v0, v1), fmaxf(v2, v3));
            if (m4 > tv[i][KTOP-1]) {
#pragma unroll
                for (int c = 0; c < 4; c++) {
                    float vv = (c == 0) ? v0 : (c == 1) ? v1 : (c == 2) ? v2 : v3;
                    int   j  = jbase + k*TJ + tx + 32*c;
                    if (vv > tv[i][KTOP-1]) {
                        tv[i][KTOP-1] = vv; ti[i][KTOP-1] = j;
#pragma unroll
                        for (int p = KTOP-1; p > 0; p--) {
                            if (tv[i][p] > tv[i][p-1]) {
                                float fv = tv[i][p]; tv[i][p] = tv[i][p-1]; tv[i][p-1] = fv;
                                int   fi = ti[i][p]; ti[i][p] = ti[i][p-1]; ti[i][p-1] = fi;
                            }
                        }
                    }
                }
            }
        }
        __syncthreads();
    }

    // warp merge, static indexing (argmax of heads + unrolled shift-down pop)
#pragma unroll
    for (int i = 0; i < 4; i++) {
#pragma unroll
        for (int s = 0; s < KTOP; s++) {
            float v = tv[i][0];
            int   j = ti[i][0];
            float bv = v; int bj = j;
#pragma unroll
            for (int off = 16; off; off >>= 1) {
                float ov = __shfl_xor_sync(0xffffffffu, bv, off);
                int   oj = __shfl_xor_sync(0xffffffffu, bj, off);
                if (ov > bv || (ov == bv && oj < bj)) { bv = ov; bj = oj; }
            }
            if (bv == v && bj == j) {
#pragma unroll
                for (int p = 0; p < KTOP-1; p++) {
                    tv[i][p] = tv[i][p+1]; ti[i][p] = ti[i][p+1];
                }
                tv[i][KTOP-1] = -INFINITY; ti[i][KTOP-1] = 0x7fffffff;
            }
            if (tx == 0) {
                int r = row0 + w*4 + i;
                g_cv[(blockIdx.y*NTOT + r)*KTOP + s] = bv;
                g_cj[(blockIdx.y*NTOT + r)*KTOP + s] = bj;
            }
        }
    }
}

// ---------------------------------------------------------------------------
// Q/K/V projections; grid = (rows/64, matrix, col-chunk). No cc loop.
__global__ __launch_bounds__(256) void qkv_kernel(
    const float* __restrict__ Wq, const float* __restrict__ bq,
    const float* __restrict__ Wk, const float* __restrict__ bk,
    const float* __restrict__ Wv, const float* __restrict__ bv) {
    __shared__ float Xs[64*RS];
    __shared__ float Ws[64*RS];

    const float *W, *bias; float* Y;
    if (blockIdx.y == 0)      { W = Wq; bias = bq; Y = g_q; }
    else if (blockIdx.y == 1) { W = Wk; bias = bk; Y = g_k; }
    else                      { W = Wv; bias = bv; Y = g_v; }

    int tid  = threadIdx.x;
    int txc  = tid & 15;
    int ty   = tid >> 4;
    int row0 = blockIdx.x * 64;
    int cc   = blockIdx.z;

    for (int idx = tid; idx < 64*16; idx += 256) {
        int r = idx >> 4, q2 = idx & 15;
        *(float4*)&Xs[r*RS + q2*4] = *(const float4*)&EGO2[(row0 + r)*EDIM + q2*4];
    }
    for (int idx = tid; idx < 64*16; idx += 256) {
        int c = idx >> 4, q2 = idx & 15;
        *(float4*)&Ws[c*RS + q2*4] = *(const float4*)&W[(cc*64 + c)*EDIM + q2*4];
    }
    __syncthreads();

    ull acc[4][4];
#pragma unroll
    for (int i = 0; i < 4; i++)
#pragma unroll
        for (int c = 0; c < 4; c++) acc[i][c] = 0ull;

#pragma unroll 4
    for (int u = 0; u < 16; u++) {
        float4 a0 = *(const float4*)&Xs[(ty*4 + 0)*RS + u*4];
        float4 a1 = *(const float4*)&Xs[(ty*4 + 1)*RS + u*4];
        float4 a2 = *(const float4*)&Xs[(ty*4 + 2)*RS + u*4];
        float4 a3 = *(const float4*)&Xs[(ty*4 + 3)*RS + u*4];
        float4 b0 = *(const float4*)&Ws[(txc +  0)*RS + u*4];
        float4 b1 = *(const float4*)&Ws[(txc + 16)*RS + u*4];
        float4 b2 = *(const float4*)&Ws[(txc + 32)*RS + u*4];
        float4 b3 = *(const float4*)&Ws[(txc + 48)*RS + u*4];
        const ull* A0 = (const ull*)&a0; const ull* A1 = (const ull*)&a1;
        const ull* A2 = (const ull*)&a2; const ull* A3 = (const ull*)&a3;
        const ull* B0 = (const ull*)&b0; const ull* B1 = (const ull*)&b1;
        const ull* B2 = (const ull*)&b2; const ull* B3 = (const ull*)&b3;
#pragma unroll
        for (int h = 0; h < 2; h++) {
            acc[0][0]=fma2(A0[h],B0[h],acc[0][0]); acc[0][1]=fma2(A0[h],B1[h],acc[0][1]);
            acc[0][2]=fma2(A0[h],B2[h],acc[0][2]); acc[0][3]=fma2(A0[h],B3[h],acc[0][3]);
            acc[1][0]=fma2(A1[h],B0[h],acc[1][0]); acc[1][1]=fma2(A1[h],B1[h],acc[1][1]);
            acc[1][2]=fma2(A1[h],B2[h],acc[1][2]); acc[1][3]=fma2(A1[h],B3[h],acc[1][3]);
            acc[2][0]=fma2(A2[h],B0[h],acc[2][0]); acc[2][1]=fma2(A2[h],B1[h],acc[2][1]);
            acc[2][2]=fma2(A2[h],B2[h],acc[2][2]); acc[2][3]=fma2(A2[h],B3[h],acc[2][3]);
            acc[3][0]=fma2(A3[h],B0[h],acc[3][0]); acc[3][1]=fma2(A3[h],B1[h],acc[3][1]);
            acc[3][2]=fma2(A3[h],B2[h],acc[3][2]); acc[3][3]=fma2(A3[h],B3[h],acc[3][3]);
        }
    }

#pragma unroll
    for (int i = 0; i < 4; i++)
#pragma unroll
        for (int c = 0; c < 4; c++) {
            int col = cc*64 + txc + 16*c;
            Y[(row0 + ty*4 + i)*DQK + col] = pairsum(acc[i][c]) + bias[col];
        }
}

// ---------------------------------------------------------------------------
// Candidate merge + gather K/V + softmax + V sum + fused mean output.
__global__ __launch_bounds__(256) void attn_kernel(
    const float* __restrict__ ue, const float* __restrict__ ie,
    float* __restrict__ out) {
    int gw   = (blockIdx.x * 256 + threadIdx.x) >> 5;
    int lane = threadIdx.x & 31;
    if (gw >= NTOT) return;

    // fused mean: out[gw] = 0.5 * (ego0[gw] + ego1[gw]); 2 floats per lane
    {
        const float* e0 = (gw < NU) ? (ue + gw*EDIM) : (ie + (gw - NU)*EDIM);
        float2 a = *(const float2*)&e0[lane*2];
        float2 b = *(const float2*)&EGO1[gw*EDIM + lane*2];
        float2 m; m.x = 0.5f*(a.x + b.x); m.y = 0.5f*(a.y + b.y);
        *(float2*)&out[gw*EDIM + lane*2] = m;
    }

    // merge NSPLIT candidate lists (value desc, index asc) — static indexing
    float cv[NSPLIT*KTOP]; int cj[NSPLIT*KTOP];
#pragma unroll
    for (int p = 0; p < NSPLIT; p++)
#pragma unroll
        for (int s = 0; s < KTOP; s++) {
            cv[p*KTOP+s] = g_cv[(p*NTOT + gw)*KTOP + s];
            cj[p*KTOP+s] = g_cj[(p*NTOT + gw)*KTOP + s];
        }
    int idx[KTOP];
#pragma unroll
    for (int s = 0; s < KTOP; s++) {
        float bv = cv[0]; int bj = cj[0]; int bp = 0;
#pragma unroll
        for (int t = 1; t < NSPLIT*KTOP; t++)
            if (cv[t] > bv || (cv[t] == bv && cj[t] < bj)) { bv = cv[t]; bj = cj[t]; bp = t; }
        idx[s] = bj;
#pragma unroll
        for (int t = 0; t < NSPLIT*KTOP; t++)
            if (t == bp) { cv[t] = -INFINITY; cj[t] = 0x7fffffff; }
    }

    float* att = out + NTOT*EDIM;
    const float4* q4 = (const float4*)(g_q + gw*DQK);
    float4 qa = q4[lane*2], qb = q4[lane*2 + 1];

    float s[KTOP];
#pragma unroll
    for (int k = 0; k < KTOP; k++) {
        const float4* k4 = (const float4*)(g_k + idx[k]*DQK);
        float4 ka = k4[lane*2], kb = k4[lane*2 + 1];
        float p = qa.x*ka.x + qa.y*ka.y + qa.z*ka.z + qa.w*ka.w
                + qb.x*kb.x + qb.y*kb.y + qb.z*kb.z + qb.w*kb.w;
#pragma unroll
        for (int off = 16; off; off >>= 1) p += __shfl_xor_sync(0xffffffffu, p, off);
        s[k] = p * (1.0f / 16.0f);
    }

    float m = s[0];
#pragma unroll
    for (int k = 1; k < KTOP; k++) m = fmaxf(m, s[k]);
    float esum = 0.f;
#pragma unroll
    for (int k = 0; k < KTOP; k++) { s[k] = expf(s[k] - m); esum += s[k]; }
    float inv = 1.f / esum;

    float4 oa = make_float4(0.f,0.f,0.f,0.f), ob = make_float4(0.f,0.f,0.f,0.f);
#pragma unroll
    for (int k = 0; k < KTOP; k++) {
        const float4* v4 = (const float4*)(g_v + idx[k]*DQK);
        float4 va = v4[lane*2], vb = v4[lane*2 + 1];
        float a = s[k] * inv;
        oa.x += a*va.x; oa.y += a*va.y; oa.z += a*va.z; oa.w += a*va.w;
        ob.x += a*vb.x; ob.y += a*vb.y; ob.z += a*vb.z; ob.w += a*vb.w;
    }
    float4* o4 = (float4*)(att + gw*DQK);
    o4[lane*2] = oa; o4[lane*2 + 1] = ob;
}

// ---------------------------------------------------------------------------
extern "C" void kernel_launch(void* const* d_in, const int* in_sizes, int n_in,
                              void* d_out, int out_size) {
    const float* ue = (const float*)d_in[0];
    const float* ie = (const float*)d_in[1];
    const int*   nr = (const int*)d_in[2];
    const int*   nc = (const int*)d_in[3];
    const float* nv = (const float*)d_in[4];
    const int*   ar = (const int*)d_in[5];
    const int*   ac = (const int*)d_in[6];
    const float* av = (const float*)d_in[7];
    const float* Wq = (const float*)d_in[8];
    const float* bq = (const float*)d_in[9];
    const float* Wk = (const float*)d_in[10];
    const float* bk = (const float*)d_in[11];
    const float* Wv = (const float*)d_in[12];
    const float* bv = (const float*)d_in[13];
    float* out = (float*)d_out;

    int nnz = in_sizes[2];
    int spmm_blocks = (nnz*16 + 255) / 256;
    int es_bytes    = 2 * TJ * RS * sizeof(float);

    cudaFuncSetAttribute(topk_pass, cudaFuncAttributeMaxDynamicSharedMemorySize, es_bytes);

    float* zbuf;
    cudaGetSymbolAddress((void**)&zbuf, g_zbuf);
    float* ego1 = zbuf;
    float* ego2 = zbuf + NE;
    float* B    = zbuf + 2*NE;

    cudaMemsetAsync(zbuf, 0, 3*NE*sizeof(float));                            // memset node
    spmm_emb   <<<spmm_blocks, 256>>>(nr, nc, nv, ue, ie, ego1, nnz);        // #1 ego1=An@ego0
    spmm_atomic<<<spmm_blocks, 256>>>(nr, nc, nv, ego1, ego2, 1.0f, nnz);    // #2 ego2=An@ego1
    spmm_atomic<<<spmm_blocks, 256>>>(ar, ac, av, ego2, B, 0.5f, nnz);       // #3 B=0.5*A@ego2
    topk_pass<<<dim3(NTOT/32, NSPLIT), 256, es_bytes>>>();                   // #4 <-- PROFILED
    qkv_kernel<<<dim3(NTOT/64, 3, 4), 256>>>(Wq, bq, Wk, bk, Wv, bv);        // #5
    attn_kernel<<<(NTOT*32 + 255)/256, 256>>>(ue, ie, out);                  // #6 merge+attn+mean
}